// round 15
// baseline (speedup 1.0000x reference)
#include <cuda_runtime.h>

#define NB   64
#define LL   4500
#define KCH  64

typedef unsigned long long u64;

__device__ __forceinline__ u64 pk(float lo, float hi) {
    u64 r; asm("mov.b64 %0, {%1,%2};" : "=l"(r) : "f"(lo), "f"(hi)); return r;
}
__device__ __forceinline__ u64 pk1(float v) { return pk(v, v); }
__device__ __forceinline__ void upk(u64 p, float& lo, float& hi) {
    asm("mov.b64 {%0,%1}, %2;" : "=f"(lo), "=f"(hi) : "l"(p));
}
__device__ __forceinline__ u64 f2(u64 a, u64 b, u64 c) {
    u64 d; asm("fma.rn.f32x2 %0, %1, %2, %3;" : "=l"(d) : "l"(a), "l"(b), "l"(c));
    return d;
}

// ---------------- scratch ----------------------------------------------------
__device__ float g_h2[NB * KCH * LL];     // conv2 output (73.7 MB)
__device__ float g_sq[NB * KCH];          // sum_l h2^2
__device__ float g_gram[NB * 64 * 36];    // 8x8 Gram (upper tri) per (n,o)
__device__ float g_coef[NB * 64 * 8];     // routing coefficients
__device__ float g_outb[NB * 64];         // effective bias per (n,o)

// ---------------- K0: zero accumulators --------------------------------------
__global__ void k0_zero() {
    int i = blockIdx.x * blockDim.x + threadIdx.x;
    if (i < NB * KCH) g_sq[i] = 0.f;
    if (i < NB * 64 * 36) g_gram[i] = 0.f;
}

// ---------------- K2: fused conv1(k=7) + conv2(k=5) + sum-of-squares ---------
// (proven scalar version from the 936us config)
#define K2_SMEM_FLOATS (64*264 + 20480 + 272 + 448 + 64)
__global__ __launch_bounds__(512) void k2_fused(const float* __restrict__ x,
                                                const float* __restrict__ w1,
                                                const float* __restrict__ w2) {
    extern __shared__ float sm[];
    float* h1s = sm;                   // [64][264], cols 0..259 used (halo 2)
    float* w2s = h1s + 64 * 264;       // [c][dk][k]  (20480)
    float* xs  = w2s + 20480;          // 266 used
    float* w1s = xs + 272;             // 448
    float* sqs = w1s + 448;            // 64
    int n  = blockIdx.y;
    int l0 = blockIdx.x * 256;
    int tid = threadIdx.x;

    for (int i = tid; i < 448; i += 512) w1s[i] = w1[i];
    for (int i = tid; i < 266; i += 512) {
        int g = l0 - 5 + i;
        xs[i] = (g >= 0 && g < LL) ? x[n * LL + g] : 0.f;
    }
    for (int i = tid; i < 20480; i += 512) {
        int k = i / 320; int r = i - k * 320; int c = r / 5; int dk = r - c * 5;
        w2s[c * 320 + dk * 64 + k] = w2[i];
    }
    if (tid < 64) sqs[tid] = 0.f;
    __syncthreads();

    for (int i = tid; i < 64 * 260; i += 512) {
        int c = i / 260; int p = i - c * 260;
        int g = l0 - 2 + p;
        float a = 0.f;
        if (g >= 0 && g < LL) {
            #pragma unroll
            for (int d = 0; d < 7; d++) a = fmaf(xs[p + d], w1s[c * 7 + d], a);
        }
        h1s[c * 264 + p] = a;
    }
    __syncthreads();

    int kg = tid >> 5, lg = tid & 31;
    int k0 = kg * 4, ll0 = lg * 8;

    u64 acc[2][8];
    #pragma unroll
    for (int a = 0; a < 2; a++)
        #pragma unroll
        for (int b = 0; b < 8; b++) acc[a][b] = 0ull;

    for (int c = 0; c < 64; c++) {
        const float* hr = h1s + c * 264 + ll0;
        float4 A = *(const float4*)(hr);
        float4 B = *(const float4*)(hr + 4);
        float4 C = *(const float4*)(hr + 8);
        float hv[12] = {A.x, A.y, A.z, A.w, B.x, B.y, B.z, B.w, C.x, C.y, C.z, C.w};
        u64 hp[12];
        #pragma unroll
        for (int t = 0; t < 12; t++) hp[t] = pk1(hv[t]);
        const u64* wr = (const u64*)(w2s + c * 320 + k0);
        #pragma unroll
        for (int dk = 0; dk < 5; dk++) {
            u64 w0 = wr[dk * 32], w1p = wr[dk * 32 + 1];
            #pragma unroll
            for (int ll = 0; ll < 8; ll++) {
                acc[0][ll] = f2(w0,  hp[ll + dk], acc[0][ll]);
                acc[1][ll] = f2(w1p, hp[ll + dk], acc[1][ll]);
            }
        }
    }

    float r[4][8];
    #pragma unroll
    for (int ll = 0; ll < 8; ll++) {
        upk(acc[0][ll], r[0][ll], r[1][ll]);
        upk(acc[1][ll], r[2][ll], r[3][ll]);
    }
    float sl[4] = {0.f, 0.f, 0.f, 0.f};
    #pragma unroll
    for (int kk = 0; kk < 4; kk++) {
        size_t row = ((size_t)n * 64 + k0 + kk) * LL;
        #pragma unroll
        for (int v = 0; v < 2; v++) {
            int gl = l0 + ll0 + v * 4;
            if (gl < LL) {
                float4 st = {r[kk][v*4+0], r[kk][v*4+1], r[kk][v*4+2], r[kk][v*4+3]};
                *(float4*)&g_h2[row + gl] = st;
                sl[kk] += st.x*st.x + st.y*st.y + st.z*st.z + st.w*st.w;
            }
        }
    }
    #pragma unroll
    for (int kk = 0; kk < 4; kk++) atomicAdd(&sqs[k0 + kk], sl[kk]);
    __syncthreads();
    if (tid < 64) atomicAdd(&g_sq[n * 64 + tid], sqs[tid]);
}

// ---------------- K3: fused squash + psi_mA conv + 8x8 Gram ------------------
__global__ __launch_bounds__(256) void k_gram(const float* __restrict__ w5,
                                              const float* __restrict__ b5) {
    __shared__ float h3s[64 * 132];
    __shared__ u64   ws2[64 * 24];
    __shared__ u64   bpk[64];
    __shared__ float invs[64];
    int n  = blockIdx.y;
    int l0 = blockIdx.x * 128;
    int tid = threadIdx.x;

    if (tid < 64) {
        invs[tid] = 1.f / (1.f + g_sq[n * 64 + tid]);
        bpk[tid]  = pk1(b5[tid]);
    }
    for (int i = tid; i < 64 * 24; i += 256) ws2[i] = pk1(w5[i]);
    __syncthreads();
    for (int i = tid; i < 64 * 130; i += 256) {
        int c = i / 130; int p = i - c * 130;
        int g = l0 - 1 + p;
        h3s[c * 132 + p] = (g >= 0 && g < LL) ? g_h2[((size_t)n*64+c)*LL + g] * invs[c]
                                              : 0.f;
    }
    __syncthreads();

    int o = tid >> 2, lc = tid & 3;
    const u64* wo = ws2 + o * 24;
    u64 bias = bpk[o];

    u64 gr[36];
    #pragma unroll
    for (int p = 0; p < 36; p++) gr[p] = 0ull;

    for (int s = 0; s < 8; s++) {
        int q  = lc + 4 * s;
        int cb = 4 * q;
        u64 vA[8], vB[8];
        #pragma unroll
        for (int i = 0; i < 8; i++) {
            u64 a = bias, b = bias;
            #pragma unroll
            for (int kh = 0; kh < 8; kh++) {
                const float* rp = h3s + (8*i + kh) * 132 + cb;
                u64 u01 = *(const u64*)rp;
                u64 u23 = *(const u64*)(rp + 2);
                u64 u45 = *(const u64*)(rp + 4);
                float d0, c1, c2, c3, c4, d5;
                upk(u01, d0, c1); upk(u23, c2, c3); upk(u45, c4, d5);
                u64 m12 = pk(c1, c2), m34 = pk(c3, c4);
                u64 w0 = wo[kh*3+0], w1 = wo[kh*3+1], w2v = wo[kh*3+2];
                a = f2(w0, u01, a); a = f2(w1, m12, a); a = f2(w2v, u23, a);
                b = f2(w0, u23, b); b = f2(w1, m34, b); b = f2(w2v, u45, b);
            }
            vA[i] = a; vB[i] = b;
        }
        int base = l0 + 4 * q;
        if (base + 3 >= LL) {
            #pragma unroll
            for (int i = 0; i < 8; i++) {
                float a0, a1, b0, b1;
                upk(vA[i], a0, a1); upk(vB[i], b0, b1);
                if (base     >= LL) a0 = 0.f;
                if (base + 1 >= LL) a1 = 0.f;
                if (base + 2 >= LL) b0 = 0.f;
                if (base + 3 >= LL) b1 = 0.f;
                vA[i] = pk(a0, a1); vB[i] = pk(b0, b1);
            }
        }
        int p = 0;
        #pragma unroll
        for (int i = 0; i < 8; i++)
            #pragma unroll
            for (int j = i; j < 8; j++) {
                gr[p] = f2(vA[i], vA[j], gr[p]);
                gr[p] = f2(vB[i], vB[j], gr[p]);
                p++;
            }
    }

    int no = n * 64 + o;
    #pragma unroll
    for (int p = 0; p < 36; p++) {
        float lo, hi; upk(gr[p], lo, hi);
        float v = lo + hi;
        v += __shfl_down_sync(0xffffffffu, v, 2, 4);
        v += __shfl_down_sync(0xffffffffu, v, 1, 4);
        if (lc == 0) atomicAdd(&g_gram[no * 36 + p], v);
    }
}

// ---------------- K4: routing from Gram -> coefficients ----------------------
__global__ void k_route(const float* __restrict__ b5) {
    int t = blockIdx.x * 256 + threadIdx.x;
    if (t >= NB * 64) return;
    int o = t & 63;

    float G[8][8];
    {
        const float* gp = g_gram + t * 36;
        int p = 0;
        for (int i = 0; i < 8; i++)
            for (int j = i; j < 8; j++) { float v = gp[p++]; G[i][j] = v; G[j][i] = v; }
    }
    float rowsum[8], tot = 0.f;
    for (int i = 0; i < 8; i++) {
        float s = 0.f;
        for (int j = 0; j < 8; j++) s += G[i][j];
        rowsum[i] = s; tot += s;
    }
    float sqn1 = tot * (1.f / 64.f);
    float inv1 = 1.f / (sqn1 + 1.f);
    float b[8], m = -1e30f;
    for (int i = 0; i < 8; i++) {
        b[i] = rowsum[i] * 0.125f * inv1;
        if (b[i] > m) m = b[i];
    }
    float e[8], se = 0.f;
    for (int i = 0; i < 8; i++) { e[i] = expf(b[i] - m); se += e[i]; }
    float ise = 1.f / se;
    float c[8];
    for (int i = 0; i < 8; i++) c[i] = e[i] * ise;
    float sqn2 = 0.f;
    for (int i = 0; i < 8; i++)
        for (int j = 0; j < 8; j++) sqn2 += c[i] * c[j] * G[i][j];
    float k = 1.f / (sqn2 + 1.f);
    float csum = 0.f;
    for (int i = 0; i < 8; i++) {
        float cf = c[i] * k;
        g_coef[t * 8 + i] = cf;
        csum += cf;
    }
    g_outb[t] = csum * b5[o];
}

// ---------------- K5: factorized output --------------------------------------
// m[kh][l] = sum_i coef[n,o,i] * h3[8i+kh][l] ;  out = outb + sum_{kh,kw} w5*m
__global__ __launch_bounds__(256) void k5_new(const float* __restrict__ w5,
                                              float* __restrict__ out) {
    __shared__ float h3s[64 * 132];     // p = 0..129 -> global l0-1+p
    __shared__ float w5s[64 * 24];
    __shared__ float cofs[64 * 8];
    __shared__ float obs[64];
    __shared__ float invs[64];
    int n  = blockIdx.y;
    int l0 = blockIdx.x * 128;
    int tid = threadIdx.x;

    if (tid < 64) {
        invs[tid] = 1.f / (1.f + g_sq[n * 64 + tid]);
        obs[tid]  = g_outb[n * 64 + tid];
    }
    for (int i = tid; i < 64 * 24; i += 256) w5s[i] = w5[i];
    for (int i = tid; i < 64 * 8; i += 256) cofs[i] = g_coef[n * 512 + i];
    __syncthreads();
    for (int i = tid; i < 64 * 130; i += 256) {
        int c = i / 130; int p = i - c * 130;
        int g = l0 - 1 + p;
        h3s[c * 132 + p] = (g >= 0 && g < LL) ? g_h2[((size_t)n*64+c)*LL + g] * invs[c]
                                              : 0.f;
    }
    __syncthreads();

    int wid = tid >> 5, lane = tid & 31;
    int lb = lane * 4;                  // p base; out l = l0 + lb + d, d 0..3
    int gl = l0 + lb;

    #pragma unroll 1
    for (int oo = 0; oo < 8; oo++) {
        int o = wid * 8 + oo;
        float cf[8];
        #pragma unroll
        for (int i = 0; i < 8; i++) cf[i] = cofs[o * 8 + i];

        float m[8][6];
        #pragma unroll
        for (int kh = 0; kh < 8; kh++)
            #pragma unroll
            for (int d = 0; d < 6; d++) m[kh][d] = 0.f;

        #pragma unroll
        for (int i = 0; i < 8; i++) {
            float c = cf[i];
            #pragma unroll
            for (int kh = 0; kh < 8; kh++) {
                const float* rp = h3s + (8 * i + kh) * 132 + lb;
                float4 A = *(const float4*)rp;
                float2 B = *(const float2*)(rp + 4);
                m[kh][0] = fmaf(c, A.x, m[kh][0]);
                m[kh][1] = fmaf(c, A.y, m[kh][1]);
                m[kh][2] = fmaf(c, A.z, m[kh][2]);
                m[kh][3] = fmaf(c, A.w, m[kh][3]);
                m[kh][4] = fmaf(c, B.x, m[kh][4]);
                m[kh][5] = fmaf(c, B.y, m[kh][5]);
            }
        }

        float ob = obs[o];
        float r0 = ob, r1 = ob, r2 = ob, r3 = ob;
        #pragma unroll
        for (int kh = 0; kh < 8; kh++) {
            float w0 = w5s[o * 24 + kh * 3 + 0];
            float w1 = w5s[o * 24 + kh * 3 + 1];
            float w2 = w5s[o * 24 + kh * 3 + 2];
            r0 = fmaf(w0, m[kh][0], r0); r0 = fmaf(w1, m[kh][1], r0); r0 = fmaf(w2, m[kh][2], r0);
            r1 = fmaf(w0, m[kh][1], r1); r1 = fmaf(w1, m[kh][2], r1); r1 = fmaf(w2, m[kh][3], r1);
            r2 = fmaf(w0, m[kh][2], r2); r2 = fmaf(w1, m[kh][3], r2); r2 = fmaf(w2, m[kh][4], r2);
            r3 = fmaf(w0, m[kh][3], r3); r3 = fmaf(w1, m[kh][4], r3); r3 = fmaf(w2, m[kh][5], r3);
        }
        if (gl < LL) {      // LL % 4 == 0 -> float4 never straddles the edge
            float4 st = {r0, r1, r2, r3};
            *(float4*)&out[((size_t)n * 64 + o) * LL + gl] = st;
        }
    }
}

// ---------------- launch -----------------------------------------------------
extern "C" void kernel_launch(void* const* d_in, const int* in_sizes, int n_in,
                              void* d_out, int out_size) {
    const float *x = nullptr, *w1 = nullptr, *w2 = nullptr, *w5 = nullptr, *b5 = nullptr;
    for (int i = 0; i < n_in; i++) {
        switch (in_sizes[i]) {
            case 288000: x  = (const float*)d_in[i]; break;
            case 448:    w1 = (const float*)d_in[i]; break;
            case 20480:  w2 = (const float*)d_in[i]; break;
            case 1536:   w5 = (const float*)d_in[i]; break;
            case 64:     b5 = (const float*)d_in[i]; break;
        }
    }
    float* out = (float*)d_out;

    const size_t smem2 = K2_SMEM_FLOATS * sizeof(float);   // 152,640 B
    cudaFuncSetAttribute(k2_fused, cudaFuncAttributeMaxDynamicSharedMemorySize,
                         (int)smem2);

    k0_zero  <<<(NB*64*36 + 255)/256, 256>>>();
    k2_fused <<<dim3(18, NB), 512, smem2>>>(x, w1, w2);
    k_gram   <<<dim3(36, NB), 256>>>(w5, b5);
    k_route  <<<16, 256>>>(b5);
    k5_new   <<<dim3(36, NB), 256>>>(w5, out);
}